// round 10
// baseline (speedup 1.0000x reference)
#include <cuda_runtime.h>

// SmartDerivatives R10: R6 topology with a coalesced lane<->data mapping.
// Lanes load CONSECUTIVE float2s of each triu row (256B/warp-request, ~6
// wavefronts per 32 descs vs R6's ~18 from stride-24B LDG.64). float2 at
// relative index r covers slots {2(r%3), 2(r%3)+1} of desc r/3; the class
// r%3 is constant per lane per unrolled position (stride 96 = 0 mod 3):
//   class0 -> row dims 0,1   class1 -> row dim2 + col dim0   class2 -> col dims 1,2
// Row sums stay uniform registers (accX/Y/Z = dims 0/1/2 for every lane);
// col side goes to warp-private padded SoA bins (conflict-free). No staging,
// no atomics, warp-local only.

constexpr int NA    = 100;
constexpr int D     = 4950;
constexpr int E     = D * 6;
constexpr int S3    = NA * 3;          // 300
constexpr int WARPS = 10;
constexpr int T     = WARPS * 32;      // 320
constexpr int AP    = 132;             // padded bin plane (132 mod 32 = 4)

struct LaneMap {                       // per-position lane constants
    int cls0, cls1, cls2;              // class (r%3) at positions 0,1,2
    int dA0,  dB0,  dC0;               // initial desc_rel (r/3)
};

__device__ __forceinline__ void elem(
    const float2* __restrict__ g2, const float* __restrict__ xrow,
    int r, int d, int cls, int i,
    float& aX, float& aY, float& aZ,
    float* __restrict__ c0, float* __restrict__ c1, float* __restrict__ c2)
{
    const float2 lv = __ldg(g2 + r);
    const float  xv = __ldg(xrow + d);
    const float  vx = lv.x * xv;
    const float  vy = lv.y * xv;
    const int    j  = i + 1 + d;
    const bool p0 = (cls == 0), p1 = (cls == 1), p2 = (cls == 2);
    if (p0) { aX += vx; aY += vy; }
    if (p1) { aZ += vx; }
    if (p1) c0[j] += vy;
    if (p2) c1[j] += vx;
    if (p2) c2[j] += vy;
}

__device__ __forceinline__ void process_row(
    int i, int lane, const LaneMap& M,
    const float* __restrict__ lb, const float* __restrict__ xb,
    float* __restrict__ c0, float* __restrict__ c1, float* __restrict__ c2,
    float* __restrict__ rowout)
{
    const int base = (i * (2 * NA - i - 1)) >> 1;   // row start desc
    const int n2   = (NA - 1 - i) * 3;              // float2 count of row

    const float2* __restrict__ g2   = reinterpret_cast<const float2*>(lb) + base * 3;
    const float*  __restrict__ xrow = xb + base;

    float aX = 0.f, aY = 0.f, aZ = 0.f;

    int rA = lane, rB = lane + 32, rC = lane + 64;
    int dA = M.dA0, dB = M.dB0, dC = M.dC0;

    while (rA < n2) {
        elem(g2, xrow, rA, dA, M.cls0, i, aX, aY, aZ, c0, c1, c2);
        if (rB < n2) elem(g2, xrow, rB, dB, M.cls1, i, aX, aY, aZ, c0, c1, c2);
        if (rC < n2) elem(g2, xrow, rC, dC, M.cls2, i, aX, aY, aZ, c0, c1, c2);
        rA += 96; rB += 96; rC += 96;
        dA += 32; dB += 32; dC += 32;     // 96 float2 = exactly 32 descs
    }

    #pragma unroll
    for (int off = 16; off; off >>= 1) {
        aX += __shfl_down_sync(0xffffffffu, aX, off);
        aY += __shfl_down_sync(0xffffffffu, aY, off);
        aZ += __shfl_down_sync(0xffffffffu, aZ, off);
    }
    if (lane == 0) {
        rowout[i * 3 + 0] = aX;
        rowout[i * 3 + 1] = aY;
        rowout[i * 3 + 2] = aZ;
    }
}

__global__ void __launch_bounds__(T)
smart_derivatives_kernel(const float* __restrict__ x,
                         const float* __restrict__ left,
                         float* __restrict__ out) {
    __shared__ float colacc[WARPS][3][AP];   // 15.8 KB: warp-private SoA bins
    __shared__ float rowout[S3];             // 1.2 KB

    const int b    = blockIdx.x;
    const int t    = threadIdx.x;
    const int w    = t >> 5;
    const int lane = t & 31;

    for (int i = t; i < WARPS * 3 * AP; i += T) (&colacc[0][0][0])[i] = 0.0f;
    if (t < S3) rowout[t] = 0.0f;
    __syncthreads();

    LaneMap M;
    M.cls0 = lane % 3;          M.dA0 = lane / 3;
    M.cls1 = (lane + 32) % 3;   M.dB0 = (lane + 32) / 3;
    M.cls2 = (lane + 64) % 3;   M.dC0 = (lane + 64) / 3;

    const float* __restrict__ lb = left + (size_t)b * E;
    const float* __restrict__ xb = x + (size_t)b * D;
    float* __restrict__ c0 = colacc[w][0];
    float* __restrict__ c1 = colacc[w][1];
    float* __restrict__ c2 = colacc[w][2];

    // Mirrored pairs per 20-row band: rows (base+w) and (base+19-w);
    // pair lengths sum to a band constant -> balanced warps.
    for (int base = 0; base < NA - 1; base += 2 * WARPS) {
        const int i1 = base + w;
        const int i2 = base + (2 * WARPS - 1) - w;
        if (i1 < NA - 1) process_row(i1, lane, M, lb, xb, c0, c1, c2, rowout);
        if (i2 < NA - 1) process_row(i2, lane, M, lb, xb, c0, c1, c2, rowout);
    }
    __syncthreads();

    // combine: out(a,d) = (rowout + sum_w colacc[w][d][a])^2, coalesced store
    if (t < S3) {
        const int a = t / 3;
        const int d = t - 3 * a;
        float s = rowout[t];
        #pragma unroll
        for (int ww = 0; ww < WARPS; ++ww) s += colacc[ww][d][a];
        out[(size_t)b * S3 + t] = s * s;
    }
}

extern "C" void kernel_launch(void* const* d_in, const int* in_sizes, int n_in,
                              void* d_out, int out_size) {
    const float* x    = (const float*)d_in[0];   // [BATCH, D] fp32
    const float* left = (const float*)d_in[1];   // [BATCH*E] fp32
    (void)in_sizes; (void)n_in; (void)out_size;

    float* out = (float*)d_out;                  // [BATCH, 300] fp32
    smart_derivatives_kernel<<<1024, T>>>(x, left, out);
}

// round 11
// speedup vs baseline: 1.9098x; 1.9098x over previous
#include <cuda_runtime.h>

// SmartDerivatives R11 = R6 (best, 39.4us) + MLP & cache-policy tuning.
// R6 was latency-bound (occ 77%, issue 43%): unroll 2 exposes only ~8
// outstanding LDGs/warp against ~37 replay-cycles/iter of stride-24B LDG.64s.
// Changes (structure untouched):
//   - #pragma unroll 4  -> ~16 LDGs in flight/warp, higher per-SM miss rate
//   - __ldcs on `left`  -> 122MB read-once stream marked evict-first, keeps
//     x rows (99x reuse per CTA) in L2
// Row i-side: register accum + shfl reduce. j-side: warp-private bins,
// stride-3-word RMW (3m mod 32 is a permutation -> conflict-free).

constexpr int NA    = 100;
constexpr int D     = 4950;          // triu descriptors
constexpr int E     = D * 6;
constexpr int S3    = NA * 3;        // 300 outputs / frame
constexpr int WARPS = 10;
constexpr int T     = WARPS * 32;    // 320 threads

__device__ __forceinline__ void process_row(
    int i, int lane,
    const float* __restrict__ lb, const float* __restrict__ xb,
    float* __restrict__ ca, float* __restrict__ rowout)
{
    const int base = (i * (2 * NA - i - 1)) >> 1;  // row start desc
    const int len  = NA - 1 - i;                   // descs in row

    float r0 = 0.0f, r1 = 0.0f, r2 = 0.0f;

    #pragma unroll 4
    for (int m = lane; m < len; m += 32) {
        const int desc = base + m;
        const float2* lp = reinterpret_cast<const float2*>(lb + desc * 6);
        const float2 l01 = __ldcs(lp);         // streaming: read-once data
        const float2 l23 = __ldcs(lp + 1);
        const float2 l45 = __ldcs(lp + 2);
        const float  xv  = __ldg(xb + desc);   // cached: reused across rows

        // atom-i side (slots 0..2)
        r0 = fmaf(l01.x, xv, r0);
        r1 = fmaf(l01.y, xv, r1);
        r2 = fmaf(l23.x, xv, r2);

        // atom-j side (slots 3..5): j unique per lane -> conflict-free RMW
        float* cj = ca + (i + 1 + m) * 3;
        cj[0] += l23.y * xv;
        cj[1] += l45.x * xv;
        cj[2] += l45.y * xv;
    }

    #pragma unroll
    for (int off = 16; off; off >>= 1) {
        r0 += __shfl_down_sync(0xffffffffu, r0, off);
        r1 += __shfl_down_sync(0xffffffffu, r1, off);
        r2 += __shfl_down_sync(0xffffffffu, r2, off);
    }
    if (lane == 0) {
        rowout[i * 3 + 0] = r0;
        rowout[i * 3 + 1] = r1;
        rowout[i * 3 + 2] = r2;
    }
}

__global__ void __launch_bounds__(T)
smart_derivatives_kernel(const float* __restrict__ x,
                         const float* __restrict__ left,
                         float* __restrict__ out) {
    __shared__ float colacc[WARPS][S3];  // 12 KB: per-warp j-side bins
    __shared__ float rowout[S3];         // 1.2 KB: i-side row sums

    const int b    = blockIdx.x;
    const int t    = threadIdx.x;
    const int w    = t >> 5;
    const int lane = t & 31;

    // zero accumulators
    for (int i = t; i < WARPS * S3; i += T) (&colacc[0][0])[i] = 0.0f;
    if (t < S3) rowout[t] = 0.0f;
    __syncthreads();

    const float* __restrict__ lb = left + (size_t)b * E;
    const float* __restrict__ xb = x + (size_t)b * D;
    float* __restrict__ ca = colacc[w];

    // Mirrored pairing per 20-row band: rows (base+w) and (base+19-w).
    // Row lengths of a pair sum to a constant -> perfect warp balance.
    for (int base = 0; base < NA - 1; base += 2 * WARPS) {
        const int i1 = base + w;
        const int i2 = base + (2 * WARPS - 1) - w;
        if (i1 < NA - 1) process_row(i1, lane, lb, xb, ca, rowout);
        if (i2 < NA - 1) process_row(i2, lane, lb, xb, ca, rowout);
    }
    __syncthreads();

    // combine: out(a,d) = (rowout + sum_w colacc[w])^2, coalesced store
    if (t < S3) {
        float s = rowout[t];
        #pragma unroll
        for (int ww = 0; ww < WARPS; ++ww) s += colacc[ww][t];
        out[(size_t)b * S3 + t] = s * s;
    }
}

extern "C" void kernel_launch(void* const* d_in, const int* in_sizes, int n_in,
                              void* d_out, int out_size) {
    const float* x    = (const float*)d_in[0];   // [BATCH, D] fp32
    const float* left = (const float*)d_in[1];   // [BATCH*E] fp32
    (void)in_sizes; (void)n_in; (void)out_size;

    float* out = (float*)d_out;                  // [BATCH, 300] fp32
    smart_derivatives_kernel<<<1024, T>>>(x, left, out);
}